// round 6
// baseline (speedup 1.0000x reference)
#include <cuda_runtime.h>

// ---------------------------------------------------------------------------
// Heisenberg-collapsed circuit:
//   <Z0> = e2x*e3x + (e0*e1) * (e2y*e3x + e2z)
// Round 6: two-kernel split (R3 structure) + phase-form trig:
//   wires 0,1,3:  e = C + R*cos(x - delta)        (1 MUFU each)
//   wire 2:       three affine forms over one sincos (2 MUFU)
// => 5 MUFU + ~16 FMA per sample (was 8 MUFU + ~24 FMA).
// ---------------------------------------------------------------------------

// K layout (padded to 20 floats, 16B aligned for float4 loads):
//  [0..2]  wire0: C, R, -delta
//  [3..5]  wire1: C, R, -delta
//  [6..8]  e2x:  K0, K1, K2
//  [9..11] e2y:  K0, K1, K2
//  [12..14]e2z:  K0, K1, K2
//  [15..17]wire3: C, R, -delta
__device__ __align__(16) float g_K[20];

struct Cpx { float r, i; };
__device__ __forceinline__ Cpx cmul(Cpx a, Cpx b) { return {a.r*b.r - a.i*b.i, a.r*b.i + a.i*b.r}; }
__device__ __forceinline__ Cpx cconj(Cpx a)       { return {a.r, -a.i}; }
__device__ __forceinline__ Cpx cadd(Cpx a, Cpx b) { return {a.r + b.r, a.i + b.i}; }
__device__ __forceinline__ Cpx csub(Cpx a, Cpx b) { return {a.r - b.r, a.i - b.i}; }
__device__ __forceinline__ Cpx cmuli(Cpx a)       { return {-a.i, a.r}; }   // i*a

// Rot(phi, theta, omega) = RZ(omega) RY(theta) RZ(phi).
__device__ void rot_mat(const float* __restrict__ w, Cpx R[4]) {
    float phi = w[0], th = w[1], om = w[2];
    float c = cosf(0.5f * th), s = sinf(0.5f * th);
    float a = 0.5f * (phi + om), b = 0.5f * (phi - om);
    Cpx ep = { cosf(a), -sinf(a) };   // exp(-i(phi+om)/2)
    Cpx em = { cosf(b),  sinf(b) };   // exp(+i(phi-om)/2)
    R[0] = {  ep.r * c,  ep.i * c };
    R[1] = { -em.r * s, -em.i * s };
    R[2] = {  em.r * s, -em.i * s };  // conj(em)*s
    R[3] = {  ep.r * c, -ep.i * c };  // conj(ep)*c
}

// K coefficients of <v| R^dag P R |v>, v = (cos x/2, -i sin x/2):
// e = K0 + K1*cos(x) + K2*sin(x). P: 0=X, 1=Y, 2=Z.
__device__ void exp_coeffs(const Cpx R[4], int P, float scale, float* K) {
    float N00, N11;
    Cpx N01;
    if (P == 2) {            // Z
        N00 = (R[0].r*R[0].r + R[0].i*R[0].i) - (R[2].r*R[2].r + R[2].i*R[2].i);
        N01 = csub(cmul(cconj(R[0]), R[1]), cmul(cconj(R[2]), R[3]));
        N11 = (R[1].r*R[1].r + R[1].i*R[1].i) - (R[3].r*R[3].r + R[3].i*R[3].i);
    } else if (P == 0) {     // X
        Cpx z02 = cmul(cconj(R[0]), R[2]);
        Cpx z13 = cmul(cconj(R[1]), R[3]);
        N00 = 2.0f * z02.r;
        N01 = cadd(cmul(cconj(R[0]), R[3]), cmul(cconj(R[2]), R[1]));
        N11 = 2.0f * z13.r;
    } else {                 // Y
        Cpx z02 = cmul(cconj(R[0]), R[2]);
        Cpx z13 = cmul(cconj(R[1]), R[3]);
        N00 = 2.0f * z02.i;
        Cpx t1 = cmuli(cmul(cconj(R[0]), R[3]));
        Cpx t2 = cmuli(cmul(cconj(R[2]), R[1]));
        N01 = csub(t2, t1);
        N11 = 2.0f * z13.i;
    }
    K[0] = 0.5f * (N00 + N11) * scale;
    K[1] = 0.5f * (N00 - N11) * scale;
    K[2] = N01.i * scale;
}

// 6 threads, one K triple each; wires 0,1,3 converted to phase form.
__global__ void precompute_k(const float* __restrict__ w) {
    int t = threadIdx.x;
    if (t >= 6) return;

    // map: 0->(w0,Z) 1->(w1,Z) 2->(w2,X*a) 3->(w2,Y*b) 4->(w2,Z*g) 5->(w3,X)
    int wire = (t == 0) ? 0 : (t == 1) ? 1 : (t == 5) ? 3 : 2;
    int P    = (t <= 1) ? 2 : (t == 2) ? 0 : (t == 3) ? 1 : (t == 4) ? 2 : 0;

    float scale = 1.0f;
    if (t >= 2 && t <= 4) {
        // alpha/beta/gamma from layer-1 wire-2 Rot: M = R^dag Z R
        Cpx R1[4];
        rot_mat(w + (1 * 4 + 2) * 3, R1);
        float M00 = (R1[0].r*R1[0].r + R1[0].i*R1[0].i)
                  - (R1[2].r*R1[2].r + R1[2].i*R1[2].i);
        Cpx M01 = csub(cmul(cconj(R1[0]), R1[1]), cmul(cconj(R1[2]), R1[3]));
        scale = (t == 2) ? M01.r : (t == 3) ? -M01.i : M00;
    }

    Cpx R[4];
    rot_mat(w + wire * 3, R);
    float K[3];
    exp_coeffs(R, P, scale, K);

    int base = t * 3;
    if (t == 0 || t == 1 || t == 5) {
        // K0 + K1 cos x + K2 sin x = K0 + Rm * cos(x - delta),
        // delta = atan2(K2, K1). Store -delta so eval does x + k[2].
        float Rm = sqrtf(K[1] * K[1] + K[2] * K[2]);
        float nd = -atan2f(K[2], K[1]);
        g_K[base + 0] = K[0];
        g_K[base + 1] = Rm;
        g_K[base + 2] = nd;
    } else {
        g_K[base + 0] = K[0];
        g_K[base + 1] = K[1];
        g_K[base + 2] = K[2];
    }
    if (t == 0) { g_K[18] = 0.0f; g_K[19] = 0.0f; }
}

__device__ __forceinline__ float eval_sample(float4 xv, const float* __restrict__ k) {
    float e0 = fmaf(k[1],  __cosf(xv.x + k[2]),  k[0]);
    float e1 = fmaf(k[4],  __cosf(xv.y + k[5]),  k[3]);
    float e3 = fmaf(k[16], __cosf(xv.w + k[17]), k[15]);
    float s2, c2;
    __sincosf(xv.z, &s2, &c2);
    float e2x = fmaf(k[7],  c2, fmaf(k[8],  s2, k[6]));
    float e2y = fmaf(k[10], c2, fmaf(k[11], s2, k[9]));
    float e2z = fmaf(k[13], c2, fmaf(k[14], s2, k[12]));
    return fmaf(e0 * e1, fmaf(e2y, e3, e2z), e2x * e3);
}

__global__ __launch_bounds__(256)
void quantum_eval(const float4* __restrict__ x, float4* __restrict__ out, int Mquads) {
    int t = blockIdx.x * blockDim.x + threadIdx.x;
    if (t >= Mquads) return;

    // Front-batch the 4 DRAM loads (MLP=4).
    const float4* p = x + 4 * (size_t)t;
    float4 xv0 = __ldg(p + 0);
    float4 xv1 = __ldg(p + 1);
    float4 xv2 = __ldg(p + 2);
    float4 xv3 = __ldg(p + 3);

    // K constants: 5 vector loads (L1/L2-resident), unpacked to registers.
    const float4* kp = (const float4*)g_K;
    float4 ka = __ldg(kp + 0);
    float4 kb = __ldg(kp + 1);
    float4 kc = __ldg(kp + 2);
    float4 kd = __ldg(kp + 3);
    float4 ke = __ldg(kp + 4);
    float k[20];
    k[0]=ka.x; k[1]=ka.y; k[2]=ka.z; k[3]=ka.w;
    k[4]=kb.x; k[5]=kb.y; k[6]=kb.z; k[7]=kb.w;
    k[8]=kc.x; k[9]=kc.y; k[10]=kc.z; k[11]=kc.w;
    k[12]=kd.x; k[13]=kd.y; k[14]=kd.z; k[15]=kd.w;
    k[16]=ke.x; k[17]=ke.y; k[18]=ke.z; k[19]=ke.w;

    float4 r;
    r.x = eval_sample(xv0, k);
    r.y = eval_sample(xv1, k);
    r.z = eval_sample(xv2, k);
    r.w = eval_sample(xv3, k);
    out[t] = r;
}

extern "C" void kernel_launch(void* const* d_in, const int* in_sizes, int n_in,
                              void* d_out, int out_size) {
    const float* x = (const float*)d_in[0];        // (64, 8192, 4) fp32
    const float* weights = (const float*)d_in[1];  // (2, 4, 3) fp32
    float* out = (float*)d_out;                    // (64, 8192, 1) fp32

    int M = in_sizes[0] / 4;                       // 524288 samples
    int Mquads = M / 4;                            // 131072

    precompute_k<<<1, 32>>>(weights);
    quantum_eval<<<(Mquads + 255) / 256, 256>>>(
        (const float4*)x, (float4*)out, Mquads);
}